// round 12
// baseline (speedup 1.0000x reference)
#include <cuda_runtime.h>
#include <cuda_bf16.h>

// WaveletTransform: x (16,3,512,512) f32 ->
//   per (b,c): [x, up(LL), up(LH), up(HL), up(HH)] -> out (16,15,512,512) f32
// Haar 2x2 analysis + 2x bilinear upsample (half-pixel centers, clamp edges).
// R4 structure with 256-bit stores (Blackwell st.global.v8.f32): each thread
// owns 4 sub-cells -> 8 output cols per row, one STG.256 per row per band.

#define BX 8            // threads x (each covers 4 sub-cells)
#define BY 8            // threads y
#define TSX 32          // sub-cells per tile, x
#define TSY 8           // sub-cells per tile, y
#define HPX (TSX + 2)   // 34 halo cols
#define HPY (TSY + 2)   // 10 halo rows

__device__ __forceinline__ void stg256_cs(float* p, const float* v) {
    asm volatile(
        "st.global.cs.v8.f32 [%0], {%1,%2,%3,%4,%5,%6,%7,%8};"
        :: "l"(p), "f"(v[0]), "f"(v[1]), "f"(v[2]), "f"(v[3]),
           "f"(v[4]), "f"(v[5]), "f"(v[6]), "f"(v[7])
        : "memory");
}

__device__ __forceinline__ void ldg256(const float* p, float* v) {
    asm volatile(
        "ld.global.nc.v8.f32 {%0,%1,%2,%3,%4,%5,%6,%7}, [%8];"
        : "=f"(v[0]), "=f"(v[1]), "=f"(v[2]), "=f"(v[3]),
          "=f"(v[4]), "=f"(v[5]), "=f"(v[6]), "=f"(v[7])
        : "l"(p));
}

__global__ __launch_bounds__(BX * BY)
void wavelet_kernel(const float* __restrict__ x, float* __restrict__ out) {
    const int plane = blockIdx.z;           // b*3 + c
    const int b = plane / 3;
    const int c = plane - 3 * b;
    const float* __restrict__ xp = x + (size_t)plane * 512 * 512;
    float* __restrict__ op = out + ((size_t)b * 15 + (size_t)c * 5) * 512 * 512;

    __shared__ float s[4][HPY][HPX];

    const int sx0 = blockIdx.x * TSX;
    const int sy0 = blockIdx.y * TSY;
    const int tid = threadIdx.y * BX + threadIdx.x;

    // This thread owns sub-cells (sy, sxp .. sxp+3).
    const int sxp = sx0 + 4 * threadIdx.x;      // first sub-cell x, mult of 4
    const int sy  = sy0 + threadIdx.y;
    const size_t row_t = (size_t)(2 * sy) * 512;
    const size_t row_b = (size_t)(2 * sy + 1) * 512;
    const size_t colo  = (size_t)(2 * sxp);     // first output col (32B aligned)

    // ---- Band 0: passthrough copy, issued first (no smem dependency) ----
    {
        float t0[8], t1[8];
        ldg256(xp + row_t + colo, t0);
        ldg256(xp + row_b + colo, t1);
        stg256_cs(op + row_t + colo, t0);
        stg256_cs(op + row_b + colo, t1);
    }

    // ---- Phase 1: Haar bands for sub-tile + 1 halo, edge-clamped ----
    #pragma unroll
    for (int idx = tid; idx < HPY * HPX; idx += BX * BY) {
        const int hy = idx / HPX;
        const int hx = idx - hy * HPX;
        int gsy = sy0 - 1 + hy; gsy = min(max(gsy, 0), 255);
        int gsx = sx0 - 1 + hx; gsx = min(max(gsx, 0), 255);
        const float2 t0 = *((const float2*)(xp + (size_t)(2 * gsy)     * 512) + gsx);
        const float2 t1 = *((const float2*)(xp + (size_t)(2 * gsy + 1) * 512) + gsx);
        const float a = t0.x, bb = t0.y, cc = t1.x, dd = t1.y;
        s[0][hy][hx] = (a + bb + cc + dd) * 0.5f;   // LL
        s[1][hy][hx] = (a + bb - cc - dd) * 0.5f;   // LH
        s[2][hy][hx] = (a - bb + cc - dd) * 0.5f;   // HL
        s[3][hy][hx] = (a - bb - cc + dd) * 0.5f;   // HH
    }
    __syncthreads();

    const int lx = 1 + 4 * threadIdx.x;         // smem x of first sub-cell
    const int ly = 1 + threadIdx.y;

    // ---- Bands 1..4: separable bilinear 2x upsample ----
    // even out col: 0.25*prev + 0.75*cur ; odd: 0.75*cur + 0.25*next
    #pragma unroll
    for (int band = 0; band < 4; band++) {
        // rows ly-1, ly, ly+1 ; cols lx-1 .. lx+4 as three float2 each
        float h[3][8];
        #pragma unroll
        for (int r = 0; r < 3; r++) {
            const float* row = &s[band][ly - 1 + r][0];
            const float2 p0 = *((const float2*)(row + lx - 1));  // lx-1, lx
            const float2 p1 = *((const float2*)(row + lx + 1));  // lx+1, lx+2
            const float2 p2 = *((const float2*)(row + lx + 3));  // lx+3, lx+4
            const float B0 = p0.x, B1 = p0.y, B2 = p1.x,
                        B3 = p1.y, B4 = p2.x, B5 = p2.y;
            h[r][0] = 0.25f * B0 + 0.75f * B1;
            h[r][1] = 0.75f * B1 + 0.25f * B2;
            h[r][2] = 0.25f * B1 + 0.75f * B2;
            h[r][3] = 0.75f * B2 + 0.25f * B3;
            h[r][4] = 0.25f * B2 + 0.75f * B3;
            h[r][5] = 0.75f * B3 + 0.25f * B4;
            h[r][6] = 0.25f * B3 + 0.75f * B4;
            h[r][7] = 0.75f * B4 + 0.25f * B5;
        }
        float o_top[8], o_bot[8];
        #pragma unroll
        for (int k = 0; k < 8; k++) {
            o_top[k] = 0.25f * h[0][k] + 0.75f * h[1][k];
            o_bot[k] = 0.75f * h[1][k] + 0.25f * h[2][k];
        }
        float* __restrict__ obp = op + (size_t)(band + 1) * 512 * 512;
        stg256_cs(obp + row_t + colo, o_top);
        stg256_cs(obp + row_b + colo, o_bot);
    }
}

extern "C" void kernel_launch(void* const* d_in, const int* in_sizes, int n_in,
                              void* d_out, int out_size) {
    const float* x = (const float*)d_in[0];
    float* out = (float*)d_out;
    dim3 block(BX, BY);
    dim3 grid(256 / TSX, 256 / TSY, 16 * 3);
    wavelet_kernel<<<grid, block>>>(x, out);
}

// round 13
// speedup vs baseline: 1.0910x; 1.0910x over previous
#include <cuda_runtime.h>
#include <cuda_bf16.h>

// WaveletTransform: x (16,3,512,512) f32 ->
//   per (b,c): [x, up(LL), up(LH), up(HL), up(HH)] -> out (16,15,512,512) f32
// Haar 2x2 analysis + 2x bilinear upsample (half-pixel centers, clamp edges).
// Each thread processes TWO adjacent sub-cells -> float4 loads/stores.
// Band-0 passthrough copy issued BEFORE the smem barrier to keep writes flowing.
// FINAL: at the measured HBM write-stream ceiling (~5.5 TB/s). Seven structural
// write-path probes (stwt/wt, full-row, 2-warp CTAs, TMA bulk, STG.256, no-smem)
// all matched or regressed vs this configuration.

#define BX 16           // threads x (each covers 2 sub-cells)
#define BY 8            // threads y
#define TSX 32          // sub-cells per tile, x
#define TSY 8           // sub-cells per tile, y
#define HPX (TSX + 2)   // 34 halo cols
#define HPY (TSY + 2)   // 10 halo rows

__global__ __launch_bounds__(BX * BY)
void wavelet_kernel(const float* __restrict__ x, float* __restrict__ out) {
    const int plane = blockIdx.z;           // b*3 + c
    const int b = plane / 3;
    const int c = plane - 3 * b;
    const float* __restrict__ xp = x + (size_t)plane * 512 * 512;
    float* __restrict__ op = out + ((size_t)b * 15 + (size_t)c * 5) * 512 * 512;

    __shared__ float s[4][HPY][HPX];

    const int sx0 = blockIdx.x * TSX;
    const int sy0 = blockIdx.y * TSY;
    const int tid = threadIdx.y * BX + threadIdx.x;

    // This thread owns sub-cells (sy, sxp) and (sy, sxp+1).
    const int sxp = sx0 + 2 * threadIdx.x;      // first sub-cell x in [0,256)
    const int sy  = sy0 + threadIdx.y;
    const size_t row_t = (size_t)(2 * sy) * 512;
    const size_t row_b = (size_t)(2 * sy + 1) * 512;
    const size_t colo  = (size_t)(2 * sxp);     // first output col (16B aligned)

    // ---- Band 0: passthrough copy, issued first (no smem dependency) ----
    {
        const float4 t0 = *((const float4*)(xp + row_t + colo));
        const float4 t1 = *((const float4*)(xp + row_b + colo));
        __stcs((float4*)(op + row_t + colo), t0);
        __stcs((float4*)(op + row_b + colo), t1);
    }

    // ---- Phase 1: Haar bands for sub-tile + 1 halo, edge-clamped ----
    #pragma unroll
    for (int idx = tid; idx < HPY * HPX; idx += BX * BY) {
        const int hy = idx / HPX;
        const int hx = idx - hy * HPX;
        int gsy = sy0 - 1 + hy; gsy = min(max(gsy, 0), 255);
        int gsx = sx0 - 1 + hx; gsx = min(max(gsx, 0), 255);
        const float2 t0 = *((const float2*)(xp + (size_t)(2 * gsy)     * 512) + gsx);
        const float2 t1 = *((const float2*)(xp + (size_t)(2 * gsy + 1) * 512) + gsx);
        const float a = t0.x, bb = t0.y, cc = t1.x, dd = t1.y;
        s[0][hy][hx] = (a + bb + cc + dd) * 0.5f;   // LL
        s[1][hy][hx] = (a + bb - cc - dd) * 0.5f;   // LH
        s[2][hy][hx] = (a - bb + cc - dd) * 0.5f;   // HL
        s[3][hy][hx] = (a - bb - cc + dd) * 0.5f;   // HH
    }
    __syncthreads();

    const int lx = 1 + 2 * threadIdx.x;         // smem x of first sub-cell
    const int ly = 1 + threadIdx.y;

    // ---- Bands 1..4: separable bilinear 2x upsample ----
    // even out col: 0.25*prev + 0.75*cur ; odd: 0.75*cur + 0.25*next
    #pragma unroll
    for (int band = 0; band < 4; band++) {
        // rows ly-1, ly, ly+1 ; cols lx-1..lx+2 as two float2 each
        float h[3][4];
        #pragma unroll
        for (int r = 0; r < 3; r++) {
            const float* row = &s[band][ly - 1 + r][0];
            const float2 p0 = *((const float2*)(row + lx - 1));  // lx-1, lx
            const float2 p1 = *((const float2*)(row + lx + 1));  // lx+1, lx+2
            h[r][0] = 0.25f * p0.x + 0.75f * p0.y;
            h[r][1] = 0.75f * p0.y + 0.25f * p1.x;
            h[r][2] = 0.25f * p0.y + 0.75f * p1.x;
            h[r][3] = 0.75f * p1.x + 0.25f * p1.y;
        }
        float4 o_top, o_bot;
        o_top.x = 0.25f * h[0][0] + 0.75f * h[1][0];
        o_top.y = 0.25f * h[0][1] + 0.75f * h[1][1];
        o_top.z = 0.25f * h[0][2] + 0.75f * h[1][2];
        o_top.w = 0.25f * h[0][3] + 0.75f * h[1][3];
        o_bot.x = 0.75f * h[1][0] + 0.25f * h[2][0];
        o_bot.y = 0.75f * h[1][1] + 0.25f * h[2][1];
        o_bot.z = 0.75f * h[1][2] + 0.25f * h[2][2];
        o_bot.w = 0.75f * h[1][3] + 0.25f * h[2][3];

        float* __restrict__ obp = op + (size_t)(band + 1) * 512 * 512;
        __stcs((float4*)(obp + row_t + colo), o_top);
        __stcs((float4*)(obp + row_b + colo), o_bot);
    }
}

extern "C" void kernel_launch(void* const* d_in, const int* in_sizes, int n_in,
                              void* d_out, int out_size) {
    const float* x = (const float*)d_in[0];
    float* out = (float*)d_out;
    dim3 block(BX, BY);
    dim3 grid(256 / TSX, 256 / TSY, 16 * 3);
    wavelet_kernel<<<grid, block>>>(x, out);
}